// round 2
// baseline (speedup 1.0000x reference)
#include <cuda_runtime.h>

#define NN 50000
#define NE 1600000
#define NP 200000
#define BN_EPS 1e-5f

// ---------------- device scratch (no allocations allowed) ----------------
__device__ int   g_cnt[NN];
__device__ int   g_start[NN + 1];
__device__ int   g_cursor[NN];
__device__ int   g_csr[NE];
__device__ float g_dis[NN];
__device__ float g_hs[(size_t)NN * 128];   // GEMM output, pre-scaled by dis[row]
__device__ float g_r [(size_t)NN * 128];   // relu(conv) output (pre-BN)
__device__ float g_u [(size_t)NN * 128];   // z3 @ fcW1[:128]
__device__ float g_v [(size_t)NN * 128];   // z3 @ fcW1[128:]
__device__ float g_stat[256];              // [0:C) sum, [C:2C) sumsq
__device__ float g_aff[256];               // [0:K) scale, [K:2K) shift (BN folded)

// ---------------- graph preprocessing ----------------
__global__ void k_zero_cnt() {
    int i = blockIdx.x * blockDim.x + threadIdx.x;
    if (i < NN) g_cnt[i] = 0;
}

__global__ void k_count(const int* __restrict__ ei) {
    int e = blockIdx.x * blockDim.x + threadIdx.x;
    if (e < NE) atomicAdd(&g_cnt[ei[NE + e]], 1);
}

// single-block exclusive scan over g_cnt -> g_start (+ zero cursors)
__global__ void k_scan() {
    __shared__ int sbuf[1024];
    __shared__ int carry;
    int t = threadIdx.x;
    if (t == 0) carry = 0;
    __syncthreads();
    for (int base = 0; base < NN; base += 1024) {
        int i = base + t;
        int v = (i < NN) ? g_cnt[i] : 0;
        sbuf[t] = v;
        __syncthreads();
        for (int off = 1; off < 1024; off <<= 1) {
            int x = (t >= off) ? sbuf[t - off] : 0;
            __syncthreads();
            sbuf[t] += x;
            __syncthreads();
        }
        int excl = sbuf[t] - v + carry;
        if (i < NN) { g_start[i] = excl; g_cursor[i] = 0; }
        __syncthreads();
        if (t == 1023) carry += sbuf[1023];
        __syncthreads();
    }
    if (t == 0) g_start[NN] = carry;   // == NE
}

__global__ void k_dis() {
    int i = blockIdx.x * blockDim.x + threadIdx.x;
    if (i < NN) g_dis[i] = rsqrtf((float)(g_cnt[i] + 1));  // +1 self loop
}

__global__ void k_fill(const int* __restrict__ ei) {
    int e = blockIdx.x * blockDim.x + threadIdx.x;
    if (e < NE) {
        int c = ei[NE + e];
        int p = g_start[c] + atomicAdd(&g_cursor[c], 1);
        g_csr[p] = ei[e];   // source node
    }
}

__global__ void k_zero_stat() {
    g_stat[threadIdx.x] = 0.f;   // 256 threads
}

// ---------------- tiled fp32 GEMM: out[m,n] = (A'[m,:] @ W)[n] * (dis?) ----
// A' = A*aff_scale + aff_shift per input channel if useAff.
__global__ void __launch_bounds__(256)
k_gemm(const float* __restrict__ A, const float* __restrict__ W,
       float* __restrict__ out, int K, int Cout, int useAff, int useDis)
{
    __shared__ float As[64][68];
    __shared__ float Bs[64][68];
    int tid = threadIdx.x;
    int tx = tid & 15, ty = tid >> 4;
    int m0 = blockIdx.x * 64, n0 = blockIdx.y * 64;
    float acc[4][4] = {};

    for (int k0 = 0; k0 < K; k0 += 64) {
        // load A tile 64 rows x 64 k-cols, transposed into As[k][m]
        #pragma unroll
        for (int i = 0; i < 4; i++) {
            int idx = tid + 256 * i;
            int r = idx >> 4, c4 = idx & 15;
            int row = m0 + r;
            float4 vv = make_float4(0.f, 0.f, 0.f, 0.f);
            if (row < NN)
                vv = *reinterpret_cast<const float4*>(A + (size_t)row * K + k0 + c4 * 4);
            if (useAff) {
                int kk = k0 + c4 * 4;
                vv.x = vv.x * g_aff[kk + 0] + g_aff[K + kk + 0];
                vv.y = vv.y * g_aff[kk + 1] + g_aff[K + kk + 1];
                vv.z = vv.z * g_aff[kk + 2] + g_aff[K + kk + 2];
                vv.w = vv.w * g_aff[kk + 3] + g_aff[K + kk + 3];
            }
            As[c4 * 4 + 0][r] = vv.x;
            As[c4 * 4 + 1][r] = vv.y;
            As[c4 * 4 + 2][r] = vv.z;
            As[c4 * 4 + 3][r] = vv.w;
        }
        // load W tile 64 k x 64 n
        #pragma unroll
        for (int i = 0; i < 4; i++) {
            int idx = tid + 256 * i;
            int kk = idx >> 4, c4 = idx & 15;
            float4 vv = *reinterpret_cast<const float4*>(
                W + (size_t)(k0 + kk) * Cout + n0 + c4 * 4);
            *reinterpret_cast<float4*>(&Bs[kk][c4 * 4]) = vv;
        }
        __syncthreads();
        #pragma unroll
        for (int kk = 0; kk < 64; kk++) {
            float4 a = *reinterpret_cast<const float4*>(&As[kk][tx * 4]);
            float4 b = *reinterpret_cast<const float4*>(&Bs[kk][ty * 4]);
            acc[0][0] += a.x * b.x; acc[0][1] += a.x * b.y; acc[0][2] += a.x * b.z; acc[0][3] += a.x * b.w;
            acc[1][0] += a.y * b.x; acc[1][1] += a.y * b.y; acc[1][2] += a.y * b.z; acc[1][3] += a.y * b.w;
            acc[2][0] += a.z * b.x; acc[2][1] += a.z * b.y; acc[2][2] += a.z * b.z; acc[2][3] += a.z * b.w;
            acc[3][0] += a.w * b.x; acc[3][1] += a.w * b.y; acc[3][2] += a.w * b.z; acc[3][3] += a.w * b.w;
        }
        __syncthreads();
    }
    #pragma unroll
    for (int i = 0; i < 4; i++) {
        int row = m0 + tx * 4 + i;
        if (row >= NN) continue;
        float d = useDis ? g_dis[row] : 1.f;
        float4 o;
        o.x = acc[i][0] * d; o.y = acc[i][1] * d; o.z = acc[i][2] * d; o.w = acc[i][3] * d;
        *reinterpret_cast<float4*>(out + (size_t)row * Cout + n0 + ty * 4) = o;
    }
}

// ---------------- CSR gather aggregation + bias + relu + BN stats ----------
// r[n,c] = relu(dis[n] * (hs[n,c] + sum_{in-nbrs} hs[src,c]) + bias[c])
template <int C>
__global__ void __launch_bounds__(256) k_agg(const float* __restrict__ bias)
{
    constexpr int V = C / 32;   // 2 or 4 floats per lane
    int warp = threadIdx.x >> 5, lane = threadIdx.x & 31;
    int n = blockIdx.x * 8 + warp;
    __shared__ float sh[2 * C];
    for (int t = threadIdx.x; t < 2 * C; t += 256) sh[t] = 0.f;
    __syncthreads();

    if (n < NN) {
        int s = g_start[n], e = g_start[n + 1];
        float bch[V];
        #pragma unroll
        for (int q = 0; q < V; q++) bch[q] = bias[lane * V + q];
        float acc[V];
        if constexpr (C == 128) {
            float4 a = *reinterpret_cast<const float4*>(g_hs + (size_t)n * C + lane * 4);
            acc[0] = a.x; acc[1] = a.y; acc[2] = a.z; acc[3] = a.w;
        } else {
            float2 a = *reinterpret_cast<const float2*>(g_hs + (size_t)n * C + lane * 2);
            acc[0] = a.x; acc[1] = a.y;
        }
        int k = s;
        for (; k + 4 <= e; k += 4) {
            int s0 = g_csr[k], s1 = g_csr[k + 1], s2 = g_csr[k + 2], s3 = g_csr[k + 3];
            if constexpr (C == 128) {
                float4 h0 = *reinterpret_cast<const float4*>(g_hs + (size_t)s0 * C + lane * 4);
                float4 h1 = *reinterpret_cast<const float4*>(g_hs + (size_t)s1 * C + lane * 4);
                float4 h2 = *reinterpret_cast<const float4*>(g_hs + (size_t)s2 * C + lane * 4);
                float4 h3 = *reinterpret_cast<const float4*>(g_hs + (size_t)s3 * C + lane * 4);
                acc[0] += h0.x + h1.x + h2.x + h3.x;
                acc[1] += h0.y + h1.y + h2.y + h3.y;
                acc[2] += h0.z + h1.z + h2.z + h3.z;
                acc[3] += h0.w + h1.w + h2.w + h3.w;
            } else {
                float2 h0 = *reinterpret_cast<const float2*>(g_hs + (size_t)s0 * C + lane * 2);
                float2 h1 = *reinterpret_cast<const float2*>(g_hs + (size_t)s1 * C + lane * 2);
                float2 h2 = *reinterpret_cast<const float2*>(g_hs + (size_t)s2 * C + lane * 2);
                float2 h3 = *reinterpret_cast<const float2*>(g_hs + (size_t)s3 * C + lane * 2);
                acc[0] += h0.x + h1.x + h2.x + h3.x;
                acc[1] += h0.y + h1.y + h2.y + h3.y;
            }
        }
        for (; k < e; k++) {
            int sn = g_csr[k];
            if constexpr (C == 128) {
                float4 h = *reinterpret_cast<const float4*>(g_hs + (size_t)sn * C + lane * 4);
                acc[0] += h.x; acc[1] += h.y; acc[2] += h.z; acc[3] += h.w;
            } else {
                float2 h = *reinterpret_cast<const float2*>(g_hs + (size_t)sn * C + lane * 2);
                acc[0] += h.x; acc[1] += h.y;
            }
        }
        float dn = g_dis[n];
        #pragma unroll
        for (int q = 0; q < V; q++) {
            int c = lane * V + q;
            float t = fmaxf(acc[q] * dn + bch[q], 0.f);
            g_r[(size_t)n * C + c] = t;
            atomicAdd(&sh[c], t);
            atomicAdd(&sh[C + c], t * t);
        }
    }
    __syncthreads();
    for (int t = threadIdx.x; t < 2 * C; t += 256)
        atomicAdd(&g_stat[t], sh[t]);
}

// ---------------- fold BN into affine scale/shift -------------------------
__global__ void k_bnfold(const float* __restrict__ gam,
                         const float* __restrict__ bet, int C)
{
    int c = threadIdx.x;
    if (c < C) {
        float mu  = g_stat[c] / (float)NN;
        float ex2 = g_stat[C + c] / (float)NN;
        float var = ex2 - mu * mu;
        float inv = rsqrtf(var + BN_EPS);
        float sc  = gam[c] * inv;
        g_aff[c]     = sc;
        g_aff[C + c] = bet[c] - mu * sc;
    }
}

// ---------------- edge-pair scoring ---------------------------------------
__global__ void __launch_bounds__(256)
k_score(const int* __restrict__ src, const int* __restrict__ dst,
        const float* __restrict__ fcb1, const float* __restrict__ fcW2,
        const float* __restrict__ fcb2, float* __restrict__ out)
{
    int warp = threadIdx.x >> 5, lane = threadIdx.x & 31;
    int p = blockIdx.x * 8 + warp;
    if (p >= NP) return;
    int s = src[p], d = dst[p];
    float4 uu = *reinterpret_cast<const float4*>(g_u + (size_t)s * 128 + lane * 4);
    float4 vv = *reinterpret_cast<const float4*>(g_v + (size_t)d * 128 + lane * 4);
    float4 bb = *reinterpret_cast<const float4*>(fcb1 + lane * 4);
    float4 ww = *reinterpret_cast<const float4*>(fcW2 + lane * 4);
    float h0 = fmaxf(uu.x + vv.x + bb.x, 0.f);
    float h1 = fmaxf(uu.y + vv.y + bb.y, 0.f);
    float h2 = fmaxf(uu.z + vv.z + bb.z, 0.f);
    float h3 = fmaxf(uu.w + vv.w + bb.w, 0.f);
    float part = h0 * ww.x + h1 * ww.y + h2 * ww.z + h3 * ww.w;
    #pragma unroll
    for (int off = 16; off; off >>= 1)
        part += __shfl_down_sync(0xffffffffu, part, off);
    if (lane == 0) out[p] = part + fcb2[0];
}

// ---------------- host launch ---------------------------------------------
extern "C" void kernel_launch(void* const* d_in, const int* in_sizes, int n_in,
                              void* d_out, int out_size)
{
    const float* x    = (const float*)d_in[0];
    const int*   ei   = (const int*)  d_in[1];
    const int*   src  = (const int*)  d_in[2];
    const int*   dst  = (const int*)  d_in[3];
    const float* W1   = (const float*)d_in[4];
    const float* b1   = (const float*)d_in[5];
    const float* W2   = (const float*)d_in[6];
    const float* b2   = (const float*)d_in[7];
    const float* W3   = (const float*)d_in[8];
    const float* b3   = (const float*)d_in[9];
    const float* g1   = (const float*)d_in[10];
    const float* bt1  = (const float*)d_in[11];
    const float* g2   = (const float*)d_in[12];
    const float* bt2  = (const float*)d_in[13];
    const float* g3   = (const float*)d_in[14];
    const float* bt3  = (const float*)d_in[15];
    const float* fcW1 = (const float*)d_in[16];
    const float* fcb1 = (const float*)d_in[17];
    const float* fcW2 = (const float*)d_in[18];
    const float* fcb2 = (const float*)d_in[19];
    float* out = (float*)d_out;

    float *hs, *r, *u, *v;
    cudaGetSymbolAddress((void**)&hs, g_hs);
    cudaGetSymbolAddress((void**)&r,  g_r);
    cudaGetSymbolAddress((void**)&u,  g_u);
    cudaGetSymbolAddress((void**)&v,  g_v);

    const int NB = (NN + 255) / 256;     // 196
    const int EB = NE / 256;             // 6250
    const int MB = (NN + 63) / 64;       // 782
    const int AB = (NN + 7) / 8;         // 6250

    // graph preprocessing: degrees, dis, CSR
    k_zero_cnt<<<NB, 256>>>();
    k_count<<<EB, 256>>>(ei);
    k_scan<<<1, 1024>>>();
    k_dis<<<NB, 256>>>();
    k_fill<<<EB, 256>>>(ei);

    // layer 1: x[N,128] @ W1[128,64] -> hs (dis-scaled); agg; BN fold
    k_gemm<<<dim3(MB, 1), 256>>>(x, W1, hs, 128, 64, 0, 1);
    k_zero_stat<<<1, 256>>>();
    k_agg<64><<<AB, 256>>>(b1);
    k_bnfold<<<1, 128>>>(g1, bt1, 64);

    // layer 2: z1[N,64] @ W2[64,128]
    k_gemm<<<dim3(MB, 2), 256>>>(r, W2, hs, 64, 128, 1, 1);
    k_zero_stat<<<1, 256>>>();
    k_agg<128><<<AB, 256>>>(b2);
    k_bnfold<<<1, 128>>>(g2, bt2, 128);

    // layer 3: z2[N,128] @ W3[128,128]
    k_gemm<<<dim3(MB, 2), 256>>>(r, W3, hs, 128, 128, 1, 1);
    k_zero_stat<<<1, 256>>>();
    k_agg<128><<<AB, 256>>>(b3);
    k_bnfold<<<1, 128>>>(g3, bt3, 128);

    // per-node MLP halves: u = z3 @ fcW1[:128,:], v = z3 @ fcW1[128:,:]
    k_gemm<<<dim3(MB, 2), 256>>>(r, fcW1,              u, 128, 128, 1, 0);
    k_gemm<<<dim3(MB, 2), 256>>>(r, fcW1 + 128 * 128,  v, 128, 128, 1, 0);

    // score pairs
    k_score<<<(NP + 7) / 8, 256>>>(src, dst, fcb1, fcW2, fcb2, out);
}

// round 3
// speedup vs baseline: 1.1188x; 1.1188x over previous
#include <cuda_runtime.h>

#define NN 50000
#define NE 1600000
#define NP 200000
#define BN_EPS 1e-5f

// ---------------- device scratch (no allocations allowed) ----------------
__device__ int   g_cnt[NN];
__device__ int   g_start[NN + 1];
__device__ int   g_cursor[NN];
__device__ int   g_csr[NE];
__device__ float g_dis[NN];
__device__ float g_hs[(size_t)NN * 128];   // GEMM output, pre-scaled by dis[row]
__device__ float g_r [(size_t)NN * 128];   // relu(conv) output (pre-BN)
__device__ float g_u [(size_t)NN * 128];   // z3 @ fcW1[:128]
__device__ float g_v [(size_t)NN * 128];   // z3 @ fcW1[128:]
__device__ float g_stat[3 * 256];          // per-layer: [0:C) sum, [C:2C) sumsq
__device__ float g_aff[256];               // [0:K) scale, [K:2K) shift (BN folded)

// ---------------- graph preprocessing ----------------
__global__ void k_zero_cnt() {
    int i = blockIdx.x * blockDim.x + threadIdx.x;
    if (i < NN) g_cnt[i] = 0;
    if (i < 3 * 256) g_stat[i] = 0.f;
}

__global__ void k_count(const int* __restrict__ ei) {
    int e = blockIdx.x * blockDim.x + threadIdx.x;
    if (e < NE) atomicAdd(&g_cnt[ei[NE + e]], 1);
}

// single-block exclusive scan over g_cnt -> g_start, zero cursors, compute dis
__global__ void __launch_bounds__(1024) k_scan() {
    __shared__ int wsum[32];
    __shared__ int carry_s;
    int t = threadIdx.x, lane = t & 31, w = t >> 5;
    if (t == 0) carry_s = 0;
    __syncthreads();
    for (int base = 0; base < NN; base += 1024) {
        int i = base + t;
        int v = (i < NN) ? g_cnt[i] : 0;
        // inclusive warp scan
        int s = v;
        #pragma unroll
        for (int off = 1; off < 32; off <<= 1) {
            int x = __shfl_up_sync(0xffffffffu, s, off);
            if (lane >= off) s += x;
        }
        if (lane == 31) wsum[w] = s;
        __syncthreads();
        if (w == 0) {
            int ws = wsum[lane];
            #pragma unroll
            for (int off = 1; off < 32; off <<= 1) {
                int x = __shfl_up_sync(0xffffffffu, ws, off);
                if (lane >= off) ws += x;
            }
            wsum[lane] = ws;
        }
        __syncthreads();
        int excl = s - v + (w ? wsum[w - 1] : 0) + carry_s;
        if (i < NN) {
            g_start[i]  = excl;
            g_cursor[i] = 0;
            g_dis[i]    = rsqrtf((float)(v + 1));   // +1 self loop
        }
        __syncthreads();
        if (t == 0) carry_s += wsum[31];
        __syncthreads();
    }
    if (t == 0) g_start[NN] = carry_s;   // == NE
}

__global__ void k_fill(const int* __restrict__ ei) {
    int e = blockIdx.x * blockDim.x + threadIdx.x;
    if (e < NE) {
        int c = ei[NE + e];
        int p = g_start[c] + atomicAdd(&g_cursor[c], 1);
        g_csr[p] = ei[e];   // source node
    }
}

// ---------------- tiled fp32 GEMM: out[m,n] = (A'[m,:] @ W)[n] * (dis?) ----
// BM=128, BK=32. A' = A*aff_scale + aff_shift per input channel if useAff.
template <int BN, int TN>
__global__ void __launch_bounds__(256)
k_gemm(const float* __restrict__ A, const float* __restrict__ W,
       float* __restrict__ out, int K, int Cout, int useAff, int useDis)
{
    constexpr int BM = 128, BK = 32, TM = 8;
    constexpr int NX = BN / TN;   // 16
    __shared__ float As[BK][BM + 4];
    __shared__ float Bs[BK][BN + 4];
    int tid = threadIdx.x;
    int tx = tid % NX, ty = tid / NX;
    int m0 = blockIdx.x * BM, n0 = blockIdx.y * BN;
    float acc[TM][TN] = {};

    for (int k0 = 0; k0 < K; k0 += BK) {
        // A tile: BM x BK, transposed into As[k][m]
        #pragma unroll
        for (int i = 0; i < 4; i++) {
            int f = tid + 256 * i;     // float4 id, 1024 total
            int r = f >> 3;            // 8 float4 per row
            int kq = f & 7;
            int row = m0 + r;
            float4 vv = make_float4(0.f, 0.f, 0.f, 0.f);
            if (row < NN)
                vv = *reinterpret_cast<const float4*>(A + (size_t)row * K + k0 + kq * 4);
            if (useAff) {
                int kk = k0 + kq * 4;
                vv.x = fmaf(vv.x, g_aff[kk + 0], g_aff[K + kk + 0]);
                vv.y = fmaf(vv.y, g_aff[kk + 1], g_aff[K + kk + 1]);
                vv.z = fmaf(vv.z, g_aff[kk + 2], g_aff[K + kk + 2]);
                vv.w = fmaf(vv.w, g_aff[kk + 3], g_aff[K + kk + 3]);
            }
            As[kq * 4 + 0][r] = vv.x;
            As[kq * 4 + 1][r] = vv.y;
            As[kq * 4 + 2][r] = vv.z;
            As[kq * 4 + 3][r] = vv.w;
        }
        // B tile: BK x BN
        #pragma unroll
        for (int i = 0; i < BN / 32; i++) {
            int f = tid + 256 * i;       // float4 id, BK*BN/4 total
            int kk = f / (BN / 4);
            int nq = f % (BN / 4);
            *reinterpret_cast<float4*>(&Bs[kk][nq * 4]) =
                *reinterpret_cast<const float4*>(W + (size_t)(k0 + kk) * Cout + n0 + nq * 4);
        }
        __syncthreads();
        #pragma unroll
        for (int kk = 0; kk < BK; kk++) {
            float a[TM], b[TN];
            #pragma unroll
            for (int j = 0; j < TM; j += 4)
                *reinterpret_cast<float4*>(&a[j]) =
                    *reinterpret_cast<const float4*>(&As[kk][ty * TM + j]);
            #pragma unroll
            for (int j = 0; j < TN; j += 4)
                *reinterpret_cast<float4*>(&b[j]) =
                    *reinterpret_cast<const float4*>(&Bs[kk][tx * TN + j]);
            #pragma unroll
            for (int i = 0; i < TM; i++)
                #pragma unroll
                for (int j = 0; j < TN; j++)
                    acc[i][j] = fmaf(a[i], b[j], acc[i][j]);
        }
        __syncthreads();
    }
    #pragma unroll
    for (int i = 0; i < TM; i++) {
        int row = m0 + ty * TM + i;
        if (row >= NN) continue;
        float d = useDis ? g_dis[row] : 1.f;
        #pragma unroll
        for (int j = 0; j < TN; j += 4) {
            float4 o;
            o.x = acc[i][j + 0] * d; o.y = acc[i][j + 1] * d;
            o.z = acc[i][j + 2] * d; o.w = acc[i][j + 3] * d;
            *reinterpret_cast<float4*>(out + (size_t)row * Cout + n0 + tx * TN + j) = o;
        }
    }
}

// ---------------- CSR gather aggregation + bias + relu + BN stats ----------
// r[n,c] = relu(dis[n] * (hs[n,c] + sum_{in-nbrs} hs[src,c]) + bias[c])
template <int C>
__global__ void __launch_bounds__(256) k_agg(const float* __restrict__ bias, int layer)
{
    constexpr int V = C / 32;   // 2 or 4 floats per lane
    int warp = threadIdx.x >> 5, lane = threadIdx.x & 31;
    int n = blockIdx.x * 8 + warp;
    float* stat = g_stat + layer * 256;
    __shared__ float sh[2 * C];
    for (int t = threadIdx.x; t < 2 * C; t += 256) sh[t] = 0.f;
    __syncthreads();

    if (n < NN) {
        int s = g_start[n], e = g_start[n + 1];
        float bch[V];
        #pragma unroll
        for (int q = 0; q < V; q++) bch[q] = bias[lane * V + q];
        float acc[V];
        if constexpr (C == 128) {
            float4 a = *reinterpret_cast<const float4*>(g_hs + (size_t)n * C + lane * 4);
            acc[0] = a.x; acc[1] = a.y; acc[2] = a.z; acc[3] = a.w;
        } else {
            float2 a = *reinterpret_cast<const float2*>(g_hs + (size_t)n * C + lane * 2);
            acc[0] = a.x; acc[1] = a.y;
        }
        int k = s;
        for (; k + 4 <= e; k += 4) {
            int s0 = g_csr[k], s1 = g_csr[k + 1], s2 = g_csr[k + 2], s3 = g_csr[k + 3];
            if constexpr (C == 128) {
                float4 h0 = *reinterpret_cast<const float4*>(g_hs + (size_t)s0 * C + lane * 4);
                float4 h1 = *reinterpret_cast<const float4*>(g_hs + (size_t)s1 * C + lane * 4);
                float4 h2 = *reinterpret_cast<const float4*>(g_hs + (size_t)s2 * C + lane * 4);
                float4 h3 = *reinterpret_cast<const float4*>(g_hs + (size_t)s3 * C + lane * 4);
                acc[0] += h0.x + h1.x + h2.x + h3.x;
                acc[1] += h0.y + h1.y + h2.y + h3.y;
                acc[2] += h0.z + h1.z + h2.z + h3.z;
                acc[3] += h0.w + h1.w + h2.w + h3.w;
            } else {
                float2 h0 = *reinterpret_cast<const float2*>(g_hs + (size_t)s0 * C + lane * 2);
                float2 h1 = *reinterpret_cast<const float2*>(g_hs + (size_t)s1 * C + lane * 2);
                float2 h2 = *reinterpret_cast<const float2*>(g_hs + (size_t)s2 * C + lane * 2);
                float2 h3 = *reinterpret_cast<const float2*>(g_hs + (size_t)s3 * C + lane * 2);
                acc[0] += h0.x + h1.x + h2.x + h3.x;
                acc[1] += h0.y + h1.y + h2.y + h3.y;
            }
        }
        for (; k < e; k++) {
            int sn = g_csr[k];
            if constexpr (C == 128) {
                float4 h = *reinterpret_cast<const float4*>(g_hs + (size_t)sn * C + lane * 4);
                acc[0] += h.x; acc[1] += h.y; acc[2] += h.z; acc[3] += h.w;
            } else {
                float2 h = *reinterpret_cast<const float2*>(g_hs + (size_t)sn * C + lane * 2);
                acc[0] += h.x; acc[1] += h.y;
            }
        }
        float dn = g_dis[n];
        #pragma unroll
        for (int q = 0; q < V; q++) {
            int c = lane * V + q;
            float t = fmaxf(acc[q] * dn + bch[q], 0.f);
            g_r[(size_t)n * C + c] = t;
            atomicAdd(&sh[c], t);
            atomicAdd(&sh[C + c], t * t);
        }
    }
    __syncthreads();
    for (int t = threadIdx.x; t < 2 * C; t += 256)
        atomicAdd(&stat[t], sh[t]);
}

// ---------------- fold BN into affine scale/shift -------------------------
__global__ void k_bnfold(const float* __restrict__ gam,
                         const float* __restrict__ bet, int C, int layer)
{
    int c = threadIdx.x;
    const float* stat = g_stat + layer * 256;
    if (c < C) {
        float mu  = stat[c] / (float)NN;
        float ex2 = stat[C + c] / (float)NN;
        float var = ex2 - mu * mu;
        float inv = rsqrtf(var + BN_EPS);
        float sc  = gam[c] * inv;
        g_aff[c]     = sc;
        g_aff[C + c] = bet[c] - mu * sc;
    }
}

// ---------------- edge-pair scoring ---------------------------------------
__global__ void __launch_bounds__(256)
k_score(const int* __restrict__ src, const int* __restrict__ dst,
        const float* __restrict__ fcb1, const float* __restrict__ fcW2,
        const float* __restrict__ fcb2, float* __restrict__ out)
{
    int warp = threadIdx.x >> 5, lane = threadIdx.x & 31;
    int p = blockIdx.x * 8 + warp;
    if (p >= NP) return;
    int s = src[p], d = dst[p];
    float4 uu = *reinterpret_cast<const float4*>(g_u + (size_t)s * 128 + lane * 4);
    float4 vv = *reinterpret_cast<const float4*>(g_v + (size_t)d * 128 + lane * 4);
    float4 bb = *reinterpret_cast<const float4*>(fcb1 + lane * 4);
    float4 ww = *reinterpret_cast<const float4*>(fcW2 + lane * 4);
    float h0 = fmaxf(uu.x + vv.x + bb.x, 0.f);
    float h1 = fmaxf(uu.y + vv.y + bb.y, 0.f);
    float h2 = fmaxf(uu.z + vv.z + bb.z, 0.f);
    float h3 = fmaxf(uu.w + vv.w + bb.w, 0.f);
    float part = h0 * ww.x + h1 * ww.y + h2 * ww.z + h3 * ww.w;
    #pragma unroll
    for (int off = 16; off; off >>= 1)
        part += __shfl_down_sync(0xffffffffu, part, off);
    if (lane == 0) out[p] = part + fcb2[0];
}

// ---------------- host launch ---------------------------------------------
extern "C" void kernel_launch(void* const* d_in, const int* in_sizes, int n_in,
                              void* d_out, int out_size)
{
    const float* x    = (const float*)d_in[0];
    const int*   ei   = (const int*)  d_in[1];
    const int*   src  = (const int*)  d_in[2];
    const int*   dst  = (const int*)  d_in[3];
    const float* W1   = (const float*)d_in[4];
    const float* b1   = (const float*)d_in[5];
    const float* W2   = (const float*)d_in[6];
    const float* b2   = (const float*)d_in[7];
    const float* W3   = (const float*)d_in[8];
    const float* b3   = (const float*)d_in[9];
    const float* g1   = (const float*)d_in[10];
    const float* bt1  = (const float*)d_in[11];
    const float* g2   = (const float*)d_in[12];
    const float* bt2  = (const float*)d_in[13];
    const float* g3   = (const float*)d_in[14];
    const float* bt3  = (const float*)d_in[15];
    const float* fcW1 = (const float*)d_in[16];
    const float* fcb1 = (const float*)d_in[17];
    const float* fcW2 = (const float*)d_in[18];
    const float* fcb2 = (const float*)d_in[19];
    float* out = (float*)d_out;

    float *hs, *r, *u, *v;
    cudaGetSymbolAddress((void**)&hs, g_hs);
    cudaGetSymbolAddress((void**)&r,  g_r);
    cudaGetSymbolAddress((void**)&u,  g_u);
    cudaGetSymbolAddress((void**)&v,  g_v);

    const int NB = (NN + 255) / 256;     // 196
    const int EB = NE / 256;             // 6250
    const int GB = (NN + 127) / 128;     // 391
    const int AB = (NN + 7) / 8;         // 6250

    // graph preprocessing: degrees, dis, CSR
    k_zero_cnt<<<NB, 256>>>();
    k_count<<<EB, 256>>>(ei);
    k_scan<<<1, 1024>>>();
    k_fill<<<EB, 256>>>(ei);

    // layer 1: x[N,128] @ W1[128,64] -> hs (dis-scaled); agg; BN fold
    k_gemm<64, 4><<<dim3(GB, 1), 256>>>(x, W1, hs, 128, 64, 0, 1);
    k_agg<64><<<AB, 256>>>(b1, 0);
    k_bnfold<<<1, 128>>>(g1, bt1, 64, 0);

    // layer 2: z1[N,64] @ W2[64,128]
    k_gemm<128, 8><<<dim3(GB, 1), 256>>>(r, W2, hs, 64, 128, 1, 1);
    k_agg<128><<<AB, 256>>>(b2, 1);
    k_bnfold<<<1, 128>>>(g2, bt2, 128, 1);

    // layer 3: z2[N,128] @ W3[128,128]
    k_gemm<128, 8><<<dim3(GB, 1), 256>>>(r, W3, hs, 128, 128, 1, 1);
    k_agg<128><<<AB, 256>>>(b3, 2);
    k_bnfold<<<1, 128>>>(g3, bt3, 128, 2);

    // per-node MLP halves: u = z3 @ fcW1[:128,:], v = z3 @ fcW1[128:,:]
    k_gemm<128, 8><<<dim3(GB, 1), 256>>>(r, fcW1,             u, 128, 128, 1, 0);
    k_gemm<128, 8><<<dim3(GB, 1), 256>>>(r, fcW1 + 128 * 128, v, 128, 128, 1, 0);

    // score pairs
    k_score<<<(NP + 7) / 8, 256>>>(src, dst, fcb1, fcW2, fcb2, out);
}

// round 4
// speedup vs baseline: 1.1618x; 1.0384x over previous
#include <cuda_runtime.h>
#include <cuda_fp16.h>

#define NN 50000
#define NE 1600000
#define NP 200000
#define BN_EPS 1e-5f

// ---------------- device scratch (no allocations allowed) ----------------
__device__ int    g_cnt[NN];
__device__ int    g_start[NN + 1];
__device__ int    g_cursor[NN];
__device__ int    g_csr[NE];
__device__ float  g_dis[NN];
__device__ __half g_hsh[(size_t)NN * 128];  // GEMM output (dis-scaled), fp16
__device__ float  g_r [(size_t)NN * 128];   // relu(conv) output (pre-BN)
__device__ float  g_u [(size_t)NN * 128];   // z3 @ fcW1[:128]
__device__ float  g_v [(size_t)NN * 128];   // z3 @ fcW1[128:]
__device__ float  g_stat[3 * 256];          // per-layer: [0:C) sum, [C:2C) sumsq

// ---------------- graph preprocessing ----------------
__global__ void k_zero_cnt() {
    int i = blockIdx.x * blockDim.x + threadIdx.x;
    if (i < NN) g_cnt[i] = 0;
    if (i < 3 * 256) g_stat[i] = 0.f;
}

__global__ void k_count(const int* __restrict__ ei) {
    int e = blockIdx.x * blockDim.x + threadIdx.x;
    if (e < NE) atomicAdd(&g_cnt[ei[NE + e]], 1);
}

// single-block exclusive scan over g_cnt -> g_start, zero cursors, compute dis
__global__ void __launch_bounds__(1024) k_scan() {
    __shared__ int wsum[32];
    __shared__ int carry_s;
    int t = threadIdx.x, lane = t & 31, w = t >> 5;
    if (t == 0) carry_s = 0;
    __syncthreads();
    for (int base = 0; base < NN; base += 1024) {
        int i = base + t;
        int v = (i < NN) ? g_cnt[i] : 0;
        int s = v;
        #pragma unroll
        for (int off = 1; off < 32; off <<= 1) {
            int x = __shfl_up_sync(0xffffffffu, s, off);
            if (lane >= off) s += x;
        }
        if (lane == 31) wsum[w] = s;
        __syncthreads();
        if (w == 0) {
            int ws = wsum[lane];
            #pragma unroll
            for (int off = 1; off < 32; off <<= 1) {
                int x = __shfl_up_sync(0xffffffffu, ws, off);
                if (lane >= off) ws += x;
            }
            wsum[lane] = ws;
        }
        __syncthreads();
        int excl = s - v + (w ? wsum[w - 1] : 0) + carry_s;
        if (i < NN) {
            g_start[i]  = excl;
            g_cursor[i] = 0;
            g_dis[i]    = rsqrtf((float)(v + 1));   // +1 self loop
        }
        __syncthreads();
        if (t == 0) carry_s += wsum[31];
        __syncthreads();
    }
    if (t == 0) g_start[NN] = carry_s;   // == NE
}

__global__ void k_fill(const int* __restrict__ ei) {
    int e = blockIdx.x * blockDim.x + threadIdx.x;
    if (e < NE) {
        int c = ei[NE + e];
        int p = g_start[c] + atomicAdd(&g_cursor[c], 1);
        g_csr[p] = ei[e];   // source node
    }
}

// ---------------- tiled fp32 GEMM -----------------------------------------
// out[m,n] = ((A*sc + off) @ W)[m,n] * (dis[m]?)   BM=128, BK=32.
// BN affine (sc,off) computed per-block from g_stat[layer] + gam/bet when gam!=null.
// OUTH: 1 -> write __half, 0 -> write float.
template <int BN, int TN, int OUTH>
__global__ void __launch_bounds__(256)
k_gemm(const float* __restrict__ A, const float* __restrict__ W,
       void* __restrict__ outp, int K, int Cout,
       const float* __restrict__ gam, const float* __restrict__ bet,
       int layer, int useDis)
{
    constexpr int BM = 128, BK = 32, TM = 8;
    constexpr int NX = BN / TN;   // 16
    __shared__ float As[BK][BM + 4];
    __shared__ float Bs[BK][BN + 4];
    __shared__ float sSc[128], sOf[128];
    int tid = threadIdx.x;
    int useAff = (gam != nullptr);
    if (useAff && tid < K) {
        const float* stat = g_stat + layer * 256;
        float mu  = stat[tid] / (float)NN;
        float ex2 = stat[K + tid] / (float)NN;
        float inv = rsqrtf(ex2 - mu * mu + BN_EPS);
        float sc  = gam[tid] * inv;
        sSc[tid] = sc;
        sOf[tid] = bet[tid] - mu * sc;
    }
    __syncthreads();

    int tx = tid % NX, ty = tid / NX;
    int m0 = blockIdx.x * BM, n0 = blockIdx.y * BN;
    float acc[TM][TN] = {};

    for (int k0 = 0; k0 < K; k0 += BK) {
        // A tile: BM x BK, transposed into As[k][m]
        #pragma unroll
        for (int i = 0; i < 4; i++) {
            int f = tid + 256 * i;     // float4 id, 1024 total
            int r = f >> 3;            // 8 float4 per row
            int kq = f & 7;
            int row = m0 + r;
            float4 vv = make_float4(0.f, 0.f, 0.f, 0.f);
            if (row < NN)
                vv = *reinterpret_cast<const float4*>(A + (size_t)row * K + k0 + kq * 4);
            if (useAff) {
                int kk = k0 + kq * 4;
                vv.x = fmaf(vv.x, sSc[kk + 0], sOf[kk + 0]);
                vv.y = fmaf(vv.y, sSc[kk + 1], sOf[kk + 1]);
                vv.z = fmaf(vv.z, sSc[kk + 2], sOf[kk + 2]);
                vv.w = fmaf(vv.w, sSc[kk + 3], sOf[kk + 3]);
            }
            As[kq * 4 + 0][r] = vv.x;
            As[kq * 4 + 1][r] = vv.y;
            As[kq * 4 + 2][r] = vv.z;
            As[kq * 4 + 3][r] = vv.w;
        }
        // B tile: BK x BN
        #pragma unroll
        for (int i = 0; i < BN / 32; i++) {
            int f = tid + 256 * i;       // float4 id, BK*BN/4 total
            int kk = f / (BN / 4);
            int nq = f % (BN / 4);
            *reinterpret_cast<float4*>(&Bs[kk][nq * 4]) =
                *reinterpret_cast<const float4*>(W + (size_t)(k0 + kk) * Cout + n0 + nq * 4);
        }
        __syncthreads();
        #pragma unroll
        for (int kk = 0; kk < BK; kk++) {
            float a[TM], b[TN];
            #pragma unroll
            for (int j = 0; j < TM; j += 4)
                *reinterpret_cast<float4*>(&a[j]) =
                    *reinterpret_cast<const float4*>(&As[kk][ty * TM + j]);
            #pragma unroll
            for (int j = 0; j < TN; j += 4)
                *reinterpret_cast<float4*>(&b[j]) =
                    *reinterpret_cast<const float4*>(&Bs[kk][tx * TN + j]);
            #pragma unroll
            for (int i = 0; i < TM; i++)
                #pragma unroll
                for (int j = 0; j < TN; j++)
                    acc[i][j] = fmaf(a[i], b[j], acc[i][j]);
        }
        __syncthreads();
    }
    #pragma unroll
    for (int i = 0; i < TM; i++) {
        int row = m0 + ty * TM + i;
        if (row >= NN) continue;
        float d = useDis ? g_dis[row] : 1.f;
        if constexpr (OUTH) {
            __half* out = (__half*)outp;
            __half2 h[TN / 2];
            #pragma unroll
            for (int j = 0; j < TN; j += 2)
                h[j / 2] = __floats2half2_rn(acc[i][j] * d, acc[i][j + 1] * d);
            if constexpr (TN == 8)
                *reinterpret_cast<uint4*>(out + (size_t)row * Cout + n0 + tx * TN) =
                    *reinterpret_cast<uint4*>(h);
            else
                *reinterpret_cast<uint2*>(out + (size_t)row * Cout + n0 + tx * TN) =
                    *reinterpret_cast<uint2*>(h);
        } else {
            float* out = (float*)outp;
            #pragma unroll
            for (int j = 0; j < TN; j += 4) {
                float4 o;
                o.x = acc[i][j + 0] * d; o.y = acc[i][j + 1] * d;
                o.z = acc[i][j + 2] * d; o.w = acc[i][j + 3] * d;
                *reinterpret_cast<float4*>(out + (size_t)row * Cout + n0 + tx * TN + j) = o;
            }
        }
    }
}

// ---------------- CSR gather aggregation + bias + relu + BN stats ----------
// r[n,c] = relu(dis[n] * (hsh[n,c] + sum_{in-nbrs} hsh[src,c]) + bias[c])
template <int C>
__global__ void __launch_bounds__(256) k_agg(const float* __restrict__ bias, int layer)
{
    constexpr int V = C / 32;   // 2 or 4 channels per lane
    int warp = threadIdx.x >> 5, lane = threadIdx.x & 31;
    int n = blockIdx.x * 8 + warp;
    float* stat = g_stat + layer * 256;
    __shared__ float sh[2 * C];
    for (int t = threadIdx.x; t < 2 * C; t += 256) sh[t] = 0.f;
    __syncthreads();

    if (n < NN) {
        int s = g_start[n], e = g_start[n + 1];
        float bch[V];
        #pragma unroll
        for (int q = 0; q < V; q++) bch[q] = bias[lane * V + q];
        float acc[V];

        auto loadrow = [&](int row, float* f) {
            if constexpr (C == 128) {
                float2 raw = *reinterpret_cast<const float2*>(
                    g_hsh + (size_t)row * C + lane * 4);
                __half2 h01 = *reinterpret_cast<__half2*>(&raw.x);
                __half2 h23 = *reinterpret_cast<__half2*>(&raw.y);
                float2 f01 = __half22float2(h01);
                float2 f23 = __half22float2(h23);
                f[0] = f01.x; f[1] = f01.y; f[2] = f23.x; f[3] = f23.y;
            } else {
                __half2 h = *reinterpret_cast<const __half2*>(
                    g_hsh + (size_t)row * C + lane * 2);
                float2 ff = __half22float2(h);
                f[0] = ff.x; f[1] = ff.y;
            }
        };

        loadrow(n, acc);
        int k = s;
        for (; k + 4 <= e; k += 4) {
            int s0 = g_csr[k], s1 = g_csr[k + 1], s2 = g_csr[k + 2], s3 = g_csr[k + 3];
            float f0[V], f1[V], f2[V], f3[V];
            loadrow(s0, f0); loadrow(s1, f1); loadrow(s2, f2); loadrow(s3, f3);
            #pragma unroll
            for (int q = 0; q < V; q++)
                acc[q] += (f0[q] + f1[q]) + (f2[q] + f3[q]);
        }
        for (; k < e; k++) {
            float f0[V];
            loadrow(g_csr[k], f0);
            #pragma unroll
            for (int q = 0; q < V; q++) acc[q] += f0[q];
        }
        float dn = g_dis[n];
        #pragma unroll
        for (int q = 0; q < V; q++) {
            int c = lane * V + q;
            float t = fmaxf(acc[q] * dn + bch[q], 0.f);
            g_r[(size_t)n * C + c] = t;
            atomicAdd(&sh[c], t);
            atomicAdd(&sh[C + c], t * t);
        }
    }
    __syncthreads();
    for (int t = threadIdx.x; t < 2 * C; t += 256)
        atomicAdd(&stat[t], sh[t]);
}

// ---------------- edge-pair scoring ---------------------------------------
__global__ void __launch_bounds__(256)
k_score(const int* __restrict__ src, const int* __restrict__ dst,
        const float* __restrict__ fcb1, const float* __restrict__ fcW2,
        const float* __restrict__ fcb2, float* __restrict__ out)
{
    int warp = threadIdx.x >> 5, lane = threadIdx.x & 31;
    int p = blockIdx.x * 8 + warp;
    if (p >= NP) return;
    int s = src[p], d = dst[p];
    float4 uu = *reinterpret_cast<const float4*>(g_u + (size_t)s * 128 + lane * 4);
    float4 vv = *reinterpret_cast<const float4*>(g_v + (size_t)d * 128 + lane * 4);
    float4 bb = *reinterpret_cast<const float4*>(fcb1 + lane * 4);
    float4 ww = *reinterpret_cast<const float4*>(fcW2 + lane * 4);
    float h0 = fmaxf(uu.x + vv.x + bb.x, 0.f);
    float h1 = fmaxf(uu.y + vv.y + bb.y, 0.f);
    float h2 = fmaxf(uu.z + vv.z + bb.z, 0.f);
    float h3 = fmaxf(uu.w + vv.w + bb.w, 0.f);
    float part = h0 * ww.x + h1 * ww.y + h2 * ww.z + h3 * ww.w;
    #pragma unroll
    for (int off = 16; off; off >>= 1)
        part += __shfl_down_sync(0xffffffffu, part, off);
    if (lane == 0) out[p] = part + fcb2[0];
}

// ---------------- host launch ---------------------------------------------
extern "C" void kernel_launch(void* const* d_in, const int* in_sizes, int n_in,
                              void* d_out, int out_size)
{
    const float* x    = (const float*)d_in[0];
    const int*   ei   = (const int*)  d_in[1];
    const int*   src  = (const int*)  d_in[2];
    const int*   dst  = (const int*)  d_in[3];
    const float* W1   = (const float*)d_in[4];
    const float* b1   = (const float*)d_in[5];
    const float* W2   = (const float*)d_in[6];
    const float* b2   = (const float*)d_in[7];
    const float* W3   = (const float*)d_in[8];
    const float* b3   = (const float*)d_in[9];
    const float* g1   = (const float*)d_in[10];
    const float* bt1  = (const float*)d_in[11];
    const float* g2   = (const float*)d_in[12];
    const float* bt2  = (const float*)d_in[13];
    const float* g3   = (const float*)d_in[14];
    const float* bt3  = (const float*)d_in[15];
    const float* fcW1 = (const float*)d_in[16];
    const float* fcb1 = (const float*)d_in[17];
    const float* fcW2 = (const float*)d_in[18];
    const float* fcb2 = (const float*)d_in[19];
    float* out = (float*)d_out;

    void *hsh; float *r, *u, *v;
    cudaGetSymbolAddress((void**)&hsh, g_hsh);
    cudaGetSymbolAddress((void**)&r,  g_r);
    cudaGetSymbolAddress((void**)&u,  g_u);
    cudaGetSymbolAddress((void**)&v,  g_v);

    const int NB = (NN + 255) / 256;     // 196
    const int EB = NE / 256;             // 6250
    const int GB = (NN + 127) / 128;     // 391
    const int AB = (NN + 7) / 8;         // 6250

    // graph preprocessing: degrees, dis, CSR
    k_zero_cnt<<<NB, 256>>>();
    k_count<<<EB, 256>>>(ei);
    k_scan<<<1, 1024>>>();
    k_fill<<<EB, 256>>>(ei);

    // layer 1: x[N,128] @ W1[128,64] -> hsh (dis-scaled, fp16); agg
    k_gemm<64, 4, 1><<<dim3(GB, 1), 256>>>(x, W1, hsh, 128, 64,
                                           nullptr, nullptr, 0, 1);
    k_agg<64><<<AB, 256>>>(b1, 0);

    // layer 2: bn1(z1)[N,64] @ W2[64,128]
    k_gemm<128, 8, 1><<<dim3(GB, 1), 256>>>(r, W2, hsh, 64, 128, g1, bt1, 0, 1);
    k_agg<128><<<AB, 256>>>(b2, 1);

    // layer 3: bn2(z2)[N,128] @ W3[128,128]
    k_gemm<128, 8, 1><<<dim3(GB, 1), 256>>>(r, W3, hsh, 128, 128, g2, bt2, 1, 1);
    k_agg<128><<<AB, 256>>>(b3, 2);

    // per-node MLP halves: u = bn3(z3) @ fcW1[:128,:], v = bn3(z3) @ fcW1[128:,:]
    k_gemm<128, 8, 0><<<dim3(GB, 1), 256>>>(r, fcW1,             u, 128, 128, g3, bt3, 2, 0);
    k_gemm<128, 8, 0><<<dim3(GB, 1), 256>>>(r, fcW1 + 128 * 128, v, 128, 128, g3, bt3, 2, 0);

    // score pairs
    k_score<<<(NP + 7) / 8, 256>>>(src, dst, fcb1, fcW2, fcb2, out);
}

// round 7
// speedup vs baseline: 1.4567x; 1.2539x over previous
#include <cuda_runtime.h>
#include <cuda_fp16.h>
#include <cuda_bf16.h>
#include <cstdint>

#define NN 50000
#define NE 1600000
#define NP 200000
#define BN_EPS 1e-5f

// ---------------- device scratch (no allocations allowed) ----------------
__device__ int    g_cnt[NN];
__device__ int    g_start[NN + 1];
__device__ int    g_cursor[NN];
__device__ int    g_csr[NE];
__device__ float  g_dis[NN];
__device__ __half g_hsh[(size_t)NN * 128];  // GEMM output (dis-scaled), fp16
__device__ float  g_r [(size_t)NN * 128];   // relu(conv) output (pre-BN)
__device__ float  g_u [(size_t)NN * 128];   // z3 @ fcW1[:128]
__device__ float  g_v [(size_t)NN * 128];   // z3 @ fcW1[128:]
__device__ float  g_stat[3 * 256];          // per-layer: [0:C) sum, [C:2C) sumsq

// ---------------- graph preprocessing ----------------
__global__ void k_zero_cnt() {
    int i = blockIdx.x * blockDim.x + threadIdx.x;
    if (i < NN) g_cnt[i] = 0;
    if (i < 3 * 256) g_stat[i] = 0.f;
}

__global__ void k_count(const int* __restrict__ ei) {
    int e = blockIdx.x * blockDim.x + threadIdx.x;
    if (e < NE) atomicAdd(&g_cnt[ei[NE + e]], 1);
}

// single-block exclusive scan over g_cnt -> g_start, zero cursors, compute dis
__global__ void __launch_bounds__(1024) k_scan() {
    __shared__ int wsum[32];
    __shared__ int carry_s;
    int t = threadIdx.x, lane = t & 31, w = t >> 5;
    if (t == 0) carry_s = 0;
    __syncthreads();
    for (int base = 0; base < NN; base += 1024) {
        int i = base + t;
        int v = (i < NN) ? g_cnt[i] : 0;
        int s = v;
        #pragma unroll
        for (int off = 1; off < 32; off <<= 1) {
            int x = __shfl_up_sync(0xffffffffu, s, off);
            if (lane >= off) s += x;
        }
        if (lane == 31) wsum[w] = s;
        __syncthreads();
        if (w == 0) {
            int ws = wsum[lane];
            #pragma unroll
            for (int off = 1; off < 32; off <<= 1) {
                int x = __shfl_up_sync(0xffffffffu, ws, off);
                if (lane >= off) ws += x;
            }
            wsum[lane] = ws;
        }
        __syncthreads();
        int excl = s - v + (w ? wsum[w - 1] : 0) + carry_s;
        if (i < NN) {
            g_start[i]  = excl;
            g_cursor[i] = 0;
            g_dis[i]    = rsqrtf((float)(v + 1));   // +1 self loop
        }
        __syncthreads();
        if (t == 0) carry_s += wsum[31];
        __syncthreads();
    }
    if (t == 0) g_start[NN] = carry_s;   // == NE
}

__global__ void k_fill(const int* __restrict__ ei) {
    int e = blockIdx.x * blockDim.x + threadIdx.x;
    if (e < NE) {
        int c = ei[NE + e];
        int p = g_start[c] + atomicAdd(&g_cursor[c], 1);
        g_csr[p] = ei[e];   // source node
    }
}

// ---------------- mma helpers ---------------------------------------------
__device__ __forceinline__ void ldsm4(uint32_t* r, uint32_t addr) {
    asm volatile("ldmatrix.sync.aligned.m8n8.x4.shared.b16 {%0,%1,%2,%3}, [%4];"
        : "=r"(r[0]), "=r"(r[1]), "=r"(r[2]), "=r"(r[3]) : "r"(addr));
}
__device__ __forceinline__ void ldsm4t(uint32_t* r, uint32_t addr) {
    asm volatile("ldmatrix.sync.aligned.m8n8.x4.trans.shared.b16 {%0,%1,%2,%3}, [%4];"
        : "=r"(r[0]), "=r"(r[1]), "=r"(r[2]), "=r"(r[3]) : "r"(addr));
}
__device__ __forceinline__ void mma16816(float* d, const uint32_t* a, const uint32_t* b) {
    asm volatile("mma.sync.aligned.m16n8k16.row.col.f32.bf16.bf16.f32 "
        "{%0,%1,%2,%3}, {%4,%5,%6,%7}, {%8,%9}, {%0,%1,%2,%3};"
        : "+f"(d[0]), "+f"(d[1]), "+f"(d[2]), "+f"(d[3])
        : "r"(a[0]), "r"(a[1]), "r"(a[2]), "r"(a[3]), "r"(b[0]), "r"(b[1]));
}
__device__ __forceinline__ void split_bf16(float v, __nv_bfloat16& h, __nv_bfloat16& l) {
    h = __float2bfloat16(v);
    l = __float2bfloat16(v - __bfloat162float(h));
}

// ---------------- tensor-core GEMM (bf16 split, fp32-equivalent) ----------
// out[m,n] = ((A*sc + off) @ W)[m,n] * (dis[m]?)    BM=128, BK=32, Cout==BN.
// Split precision: A ~ Ah+Al, W ~ Bh+Bl; acc += AhBh + AhBl + AlBh.
// OUTH: 1 -> write __half, 0 -> write float.
template <int BN, int WN, int OUTH>
__global__ void __launch_bounds__(256)
k_gemm(const float* __restrict__ A, const float* __restrict__ W,
       void* __restrict__ outp, int K,
       const float* __restrict__ gam, const float* __restrict__ bet,
       int layer, int useDis)
{
    constexpr int BM = 128, BK = 32;
    constexpr int LDA = BK + 8;        // 40 halves (conflict-free ldsm)
    constexpr int LDB = BN + 8;        // 136 / 72 halves
    constexpr int NF = WN / 8;         // n-frags per warp (8 or 4)
    __shared__ __align__(16) __nv_bfloat16 Ah[BM * LDA], Al[BM * LDA];
    __shared__ __align__(16) __nv_bfloat16 Bh[BK * LDB], Bl[BK * LDB];
    __shared__ float sSc[128], sOf[128];

    int tid = threadIdx.x;
    int useAff = (gam != nullptr);
    if (useAff && tid < K) {
        const float* stat = g_stat + layer * 256;
        float mu  = stat[tid] / (float)NN;
        float ex2 = stat[K + tid] / (float)NN;
        float inv = rsqrtf(ex2 - mu * mu + BN_EPS);
        float sc  = gam[tid] * inv;
        sSc[tid] = sc;
        sOf[tid] = bet[tid] - mu * sc;
    }
    __syncthreads();

    int lane = tid & 31, w = tid >> 5;
    int wm = (w & 3) * 32;        // warp m offset within tile
    int wn = (w >> 2) * WN;       // warp n offset
    int m0 = blockIdx.x * BM;

    uint32_t ahB = (uint32_t)__cvta_generic_to_shared(Ah);
    uint32_t alB = (uint32_t)__cvta_generic_to_shared(Al);
    uint32_t bhB = (uint32_t)__cvta_generic_to_shared(Bh);
    uint32_t blB = (uint32_t)__cvta_generic_to_shared(Bl);

    float acc[2][NF][4];
    #pragma unroll
    for (int i = 0; i < 2; i++)
        #pragma unroll
        for (int j = 0; j < NF; j++)
            #pragma unroll
            for (int q = 0; q < 4; q++) acc[i][j][q] = 0.f;

    for (int k0 = 0; k0 < K; k0 += BK) {
        // ---- load + split A tile: BM x BK ----
        #pragma unroll
        for (int f = 0; f < BM * BK / 4 / 256; f++) {
            int fid = tid + f * 256;
            int r = fid >> 3, kq = fid & 7;
            int row = m0 + r;
            float4 vv = make_float4(0.f, 0.f, 0.f, 0.f);
            if (row < NN)
                vv = *reinterpret_cast<const float4*>(A + (size_t)row * K + k0 + kq * 4);
            if (useAff) {
                int kk = k0 + kq * 4;
                vv.x = fmaf(vv.x, sSc[kk + 0], sOf[kk + 0]);
                vv.y = fmaf(vv.y, sSc[kk + 1], sOf[kk + 1]);
                vv.z = fmaf(vv.z, sSc[kk + 2], sOf[kk + 2]);
                vv.w = fmaf(vv.w, sSc[kk + 3], sOf[kk + 3]);
            }
            float vs[4] = {vv.x, vv.y, vv.z, vv.w};
            #pragma unroll
            for (int j = 0; j < 4; j++) {
                __nv_bfloat16 h, l;
                split_bf16(vs[j], h, l);
                Ah[r * LDA + kq * 4 + j] = h;
                Al[r * LDA + kq * 4 + j] = l;
            }
        }
        // ---- load + split B tile: BK x BN ----
        #pragma unroll
        for (int f = 0; f < BK * BN / 4 / 256; f++) {
            int fid = tid + f * 256;
            int kk = fid / (BN / 4);
            int nq = fid % (BN / 4);
            float4 vv = *reinterpret_cast<const float4*>(
                W + (size_t)(k0 + kk) * BN + nq * 4);
            float vs[4] = {vv.x, vv.y, vv.z, vv.w};
            #pragma unroll
            for (int j = 0; j < 4; j++) {
                __nv_bfloat16 h, l;
                split_bf16(vs[j], h, l);
                Bh[kk * LDB + nq * 4 + j] = h;
                Bl[kk * LDB + nq * 4 + j] = l;
            }
        }
        __syncthreads();

        #pragma unroll
        for (int ks = 0; ks < BK / 16; ks++) {
            int kk = ks * 16;
            // A fragments (m32 x k16), hi+lo planes
            uint32_t afh[2][4], afl[2][4];
            #pragma unroll
            for (int mf = 0; mf < 2; mf++) {
                uint32_t off = ((wm + mf * 16 + (lane & 15)) * LDA
                                + kk + (lane >> 4) * 8) * 2;
                ldsm4(afh[mf], ahB + off);
                ldsm4(afl[mf], alB + off);
            }
            // B chunks of n16
            #pragma unroll
            for (int ch = 0; ch < NF / 2; ch++) {
                uint32_t bfh[4], bfl[4];
                uint32_t off = ((kk + (lane & 15)) * LDB
                                + wn + ch * 16 + (lane >> 4) * 8) * 2;
                ldsm4t(bfh, bhB + off);
                ldsm4t(bfl, blB + off);
                #pragma unroll
                for (int mf = 0; mf < 2; mf++) {
                    #pragma unroll
                    for (int sub = 0; sub < 2; sub++) {
                        float* d = acc[mf][ch * 2 + sub];
                        mma16816(d, afh[mf], &bfh[sub * 2]);
                        mma16816(d, afh[mf], &bfl[sub * 2]);
                        mma16816(d, afl[mf], &bfh[sub * 2]);
                    }
                }
            }
        }
        __syncthreads();
    }

    // ---- epilogue ----
    #pragma unroll
    for (int mf = 0; mf < 2; mf++) {
        int rbase = m0 + wm + mf * 16 + (lane >> 2);
        #pragma unroll
        for (int half = 0; half < 2; half++) {
            int row = rbase + half * 8;
            if (row >= NN) continue;
            float d = useDis ? g_dis[row] : 1.f;
            #pragma unroll
            for (int nf = 0; nf < NF; nf++) {
                int col = wn + nf * 8 + (lane & 3) * 2;
                float v0 = acc[mf][nf][half * 2 + 0] * d;
                float v1 = acc[mf][nf][half * 2 + 1] * d;
                if constexpr (OUTH) {
                    __half2 hv = __floats2half2_rn(v0, v1);
                    *reinterpret_cast<__half2*>((__half*)outp + (size_t)row * BN + col) = hv;
                } else {
                    float2 fv = make_float2(v0, v1);
                    *reinterpret_cast<float2*>((float*)outp + (size_t)row * BN + col) = fv;
                }
            }
        }
    }
}

// ---------------- CSR gather aggregation + bias + relu + BN stats ----------
// r[n,c] = relu(dis[n] * (hsh[n,c] + sum_{in-nbrs} hsh[src,c]) + bias[c])
template <int C>
__global__ void __launch_bounds__(256) k_agg(const float* __restrict__ bias, int layer)
{
    constexpr int V = C / 32;   // 2 or 4 channels per lane
    int warp = threadIdx.x >> 5, lane = threadIdx.x & 31;
    int n = blockIdx.x * 8 + warp;
    float* stat = g_stat + layer * 256;
    __shared__ float sh[2 * C];
    for (int t = threadIdx.x; t < 2 * C; t += 256) sh[t] = 0.f;
    __syncthreads();

    if (n < NN) {
        int s = g_start[n], e = g_start[n + 1];
        float bch[V];
        #pragma unroll
        for (int q = 0; q < V; q++) bch[q] = bias[lane * V + q];
        float acc[V];

        auto loadrow = [&](int row, float* f) {
            if constexpr (C == 128) {
                float2 raw = *reinterpret_cast<const float2*>(
                    g_hsh + (size_t)row * C + lane * 4);
                __half2 h01 = *reinterpret_cast<__half2*>(&raw.x);
                __half2 h23 = *reinterpret_cast<__half2*>(&raw.y);
                float2 f01 = __half22float2(h01);
                float2 f23 = __half22float2(h23);
                f[0] = f01.x; f[1] = f01.y; f[2] = f23.x; f[3] = f23.y;
            } else {
                __half2 h = *reinterpret_cast<const __half2*>(
                    g_hsh + (size_t)row * C + lane * 2);
                float2 ff = __half22float2(h);
                f[0] = ff.x; f[1] = ff.y;
            }
        };

        loadrow(n, acc);
        int k = s;
        for (; k + 4 <= e; k += 4) {
            int s0 = g_csr[k], s1 = g_csr[k + 1], s2 = g_csr[k + 2], s3 = g_csr[k + 3];
            float f0[V], f1[V], f2[V], f3[V];
            loadrow(s0, f0); loadrow(s1, f1); loadrow(s2, f2); loadrow(s3, f3);
            #pragma unroll
            for (int q = 0; q < V; q++)
                acc[q] += (f0[q] + f1[q]) + (f2[q] + f3[q]);
        }
        for (; k < e; k++) {
            float f0[V];
            loadrow(g_csr[k], f0);
            #pragma unroll
            for (int q = 0; q < V; q++) acc[q] += f0[q];
        }
        float dn = g_dis[n];
        #pragma unroll
        for (int q = 0; q < V; q++) {
            int c = lane * V + q;
            float t = fmaxf(acc[q] * dn + bch[q], 0.f);
            g_r[(size_t)n * C + c] = t;
            atomicAdd(&sh[c], t);
            atomicAdd(&sh[C + c], t * t);
        }
    }
    __syncthreads();
    for (int t = threadIdx.x; t < 2 * C; t += 256)
        atomicAdd(&stat[t], sh[t]);
}

// ---------------- edge-pair scoring ---------------------------------------
__global__ void __launch_bounds__(256)
k_score(const int* __restrict__ src, const int* __restrict__ dst,
        const float* __restrict__ fcb1, const float* __restrict__ fcW2,
        const float* __restrict__ fcb2, float* __restrict__ out)
{
    int warp = threadIdx.x >> 5, lane = threadIdx.x & 31;
    int p = blockIdx.x * 8 + warp;
    if (p >= NP) return;
    int s = src[p], d = dst[p];
    float4 uu = *reinterpret_cast<const float4*>(g_u + (size_t)s * 128 + lane * 4);
    float4 vv = *reinterpret_cast<const float4*>(g_v + (size_t)d * 128 + lane * 4);
    float4 bb = *reinterpret_cast<const float4*>(fcb1 + lane * 4);
    float4 ww = *reinterpret_cast<const float4*>(fcW2 + lane * 4);
    float h0 = fmaxf(uu.x + vv.x + bb.x, 0.f);
    float h1 = fmaxf(uu.y + vv.y + bb.y, 0.f);
    float h2 = fmaxf(uu.z + vv.z + bb.z, 0.f);
    float h3 = fmaxf(uu.w + vv.w + bb.w, 0.f);
    float part = h0 * ww.x + h1 * ww.y + h2 * ww.z + h3 * ww.w;
    #pragma unroll
    for (int off = 16; off; off >>= 1)
        part += __shfl_down_sync(0xffffffffu, part, off);
    if (lane == 0) out[p] = part + fcb2[0];
}

// ---------------- host launch ---------------------------------------------
extern "C" void kernel_launch(void* const* d_in, const int* in_sizes, int n_in,
                              void* d_out, int out_size)
{
    const float* x    = (const float*)d_in[0];
    const int*   ei   = (const int*)  d_in[1];
    const int*   src  = (const int*)  d_in[2];
    const int*   dst  = (const int*)  d_in[3];
    const float* W1   = (const float*)d_in[4];
    const float* b1   = (const float*)d_in[5];
    const float* W2   = (const float*)d_in[6];
    const float* b2   = (const float*)d_in[7];
    const float* W3   = (const float*)d_in[8];
    const float* b3   = (const float*)d_in[9];
    const float* g1   = (const float*)d_in[10];
    const float* bt1  = (const float*)d_in[11];
    const float* g2   = (const float*)d_in[12];
    const float* bt2  = (const float*)d_in[13];
    const float* g3   = (const float*)d_in[14];
    const float* bt3  = (const float*)d_in[15];
    const float* fcW1 = (const float*)d_in[16];
    const float* fcb1 = (const float*)d_in[17];
    const float* fcW2 = (const float*)d_in[18];
    const float* fcb2 = (const float*)d_in[19];
    float* out = (float*)d_out;

    void *hsh; float *r, *u, *v;
    cudaGetSymbolAddress((void**)&hsh, g_hsh);
    cudaGetSymbolAddress((void**)&r,  g_r);
    cudaGetSymbolAddress((void**)&u,  g_u);
    cudaGetSymbolAddress((void**)&v,  g_v);

    const int NB = (NN + 255) / 256;     // 196
    const int EB = NE / 256;             // 6250
    const int GB = (NN + 127) / 128;     // 391
    const int AB = (NN + 7) / 8;         // 6250

    // graph preprocessing: degrees, dis, CSR
    k_zero_cnt<<<NB, 256>>>();
    k_count<<<EB, 256>>>(ei);
    k_scan<<<1, 1024>>>();
    k_fill<<<EB, 256>>>(ei);

    // layer 1: x[N,128] @ W1[128,64] -> hsh (dis-scaled, fp16); agg
    k_gemm<64, 32, 1><<<GB, 256>>>(x, W1, hsh, 128, nullptr, nullptr, 0, 1);
    k_agg<64><<<AB, 256>>>(b1, 0);

    // layer 2: bn1(z1)[N,64] @ W2[64,128]
    k_gemm<128, 64, 1><<<GB, 256>>>(r, W2, hsh, 64, g1, bt1, 0, 1);
    k_agg<128><<<AB, 256>>>(b2, 1);

    // layer 3: bn2(z2)[N,128] @ W3[128,128]
    k_gemm<128, 64, 1><<<GB, 256>>>(r, W3, hsh, 128, g2, bt2, 1, 1);
    k_agg<128><<<AB, 256>>>(b3, 2);

    // per-node MLP halves: u = bn3(z3) @ fcW1[:128,:], v = bn3(z3) @ fcW1[128:,:]
    k_gemm<128, 64, 0><<<GB, 256>>>(r, fcW1,             u, 128, g3, bt3, 2, 0);
    k_gemm<128, 64, 0><<<GB, 256>>>(r, fcW1 + 128 * 128, v, 128, g3, bt3, 2, 0);

    // score pairs
    k_score<<<(NP + 7) / 8, 256>>>(src, dst, fcb1, fcW2, fcb2, out);
}

// round 8
// speedup vs baseline: 1.6307x; 1.1194x over previous
#include <cuda_runtime.h>
#include <cuda_fp16.h>
#include <cuda_bf16.h>
#include <cstdint>

#define NN 50000
#define NE 1600000
#define NP 200000
#define BN_EPS 1e-5f

// ---------------- device scratch (no allocations allowed) ----------------
__device__ int    g_cnt[NN];
__device__ int    g_start[NN + 1];
__device__ int    g_rank[NE];
__device__ int    g_csr[NE];
__device__ float  g_dis[NN];
__device__ __half g_hsh[(size_t)NN * 128];  // GEMM output (dis-scaled), fp16
__device__ float  g_r [(size_t)NN * 128];   // relu(conv) output (pre-BN)
__device__ float  g_uv[(size_t)NN * 256];   // [*,0:128)=z@fcW1[:128]; [*,128:256)=z@fcW1[128:]
__device__ float  g_stat[3 * 256];          // per-layer: [0:C) sum, [C:2C) sumsq

// ---------------- graph preprocessing ----------------
__global__ void k_zero_cnt() {
    int i = blockIdx.x * blockDim.x + threadIdx.x;
    if (i < NN) g_cnt[i] = 0;
    if (i < 3 * 256) g_stat[i] = 0.f;
}

__global__ void k_count(const int* __restrict__ ei) {
    int e = blockIdx.x * blockDim.x + threadIdx.x;
    if (e < NE) g_rank[e] = atomicAdd(&g_cnt[ei[NE + e]], 1);
}

// single-block exclusive scan over g_cnt -> g_start, compute dis
__global__ void __launch_bounds__(1024) k_scan() {
    __shared__ int wsum[32];
    __shared__ int carry_s;
    int t = threadIdx.x, lane = t & 31, w = t >> 5;
    if (t == 0) carry_s = 0;
    __syncthreads();
    for (int base = 0; base < NN; base += 1024) {
        int i = base + t;
        int v = (i < NN) ? g_cnt[i] : 0;
        int s = v;
        #pragma unroll
        for (int off = 1; off < 32; off <<= 1) {
            int x = __shfl_up_sync(0xffffffffu, s, off);
            if (lane >= off) s += x;
        }
        if (lane == 31) wsum[w] = s;
        __syncthreads();
        if (w == 0) {
            int ws = wsum[lane];
            #pragma unroll
            for (int off = 1; off < 32; off <<= 1) {
                int x = __shfl_up_sync(0xffffffffu, ws, off);
                if (lane >= off) ws += x;
            }
            wsum[lane] = ws;
        }
        __syncthreads();
        int excl = s - v + (w ? wsum[w - 1] : 0) + carry_s;
        if (i < NN) {
            g_start[i] = excl;
            g_dis[i]   = rsqrtf((float)(v + 1));   // +1 self loop
        }
        __syncthreads();
        if (t == 0) carry_s += wsum[31];
        __syncthreads();
    }
    if (t == 0) g_start[NN] = carry_s;   // == NE
}

__global__ void k_fill(const int* __restrict__ ei) {
    int e = blockIdx.x * blockDim.x + threadIdx.x;
    if (e < NE) {
        int c = ei[NE + e];
        g_csr[g_start[c] + g_rank[e]] = ei[e];   // source node
    }
}

// ---------------- mma helpers ---------------------------------------------
__device__ __forceinline__ void ldsm4(uint32_t* r, uint32_t addr) {
    asm volatile("ldmatrix.sync.aligned.m8n8.x4.shared.b16 {%0,%1,%2,%3}, [%4];"
        : "=r"(r[0]), "=r"(r[1]), "=r"(r[2]), "=r"(r[3]) : "r"(addr));
}
__device__ __forceinline__ void ldsm4t(uint32_t* r, uint32_t addr) {
    asm volatile("ldmatrix.sync.aligned.m8n8.x4.trans.shared.b16 {%0,%1,%2,%3}, [%4];"
        : "=r"(r[0]), "=r"(r[1]), "=r"(r[2]), "=r"(r[3]) : "r"(addr));
}
__device__ __forceinline__ void mma16816(float* d, const uint32_t* a, const uint32_t* b) {
    asm volatile("mma.sync.aligned.m16n8k16.row.col.f32.bf16.bf16.f32 "
        "{%0,%1,%2,%3}, {%4,%5,%6,%7}, {%8,%9}, {%0,%1,%2,%3};"
        : "+f"(d[0]), "+f"(d[1]), "+f"(d[2]), "+f"(d[3])
        : "r"(a[0]), "r"(a[1]), "r"(a[2]), "r"(a[3]), "r"(b[0]), "r"(b[1]));
}
__device__ __forceinline__ void split_bf16(float v, __nv_bfloat16& h, __nv_bfloat16& l) {
    h = __float2bfloat16(v);
    l = __float2bfloat16(v - __bfloat162float(h));
}

// ---------------- tensor-core GEMM (bf16 split, fp32-equivalent) ----------
// out[m, ncolBase+n] = ((A*sc + off) @ Wreg)[m,n] * (dis[m]?)
// BM=128, BK=32. Wreg = W + blockIdx.y * wRegStride (fused multi-region GEMMs).
// outStride = row stride of output. OUTH: 1 -> write __half, 0 -> write float.
// Register-prefetch double buffering over the BK loop.
template <int BN, int WN, int OUTH>
__global__ void __launch_bounds__(256)
k_gemm(const float* __restrict__ A, const float* __restrict__ W,
       void* __restrict__ outp, int K,
       const float* __restrict__ gam, const float* __restrict__ bet,
       int layer, int useDis, int wRegStride, int outStride)
{
    constexpr int BM = 128, BK = 32;
    constexpr int LDA = BK + 8;        // 40 halves (16B-aligned rows)
    constexpr int LDB = BN + 8;        // 136 / 72 halves (16B-aligned rows)
    constexpr int NF = WN / 8;         // n-frags per warp
    constexpr int NAR = 4;             // A float4 loads per thread
    constexpr int NBR = BN / 32;       // B float4 loads per thread
    __shared__ __align__(16) __nv_bfloat16 Ah[BM * LDA], Al[BM * LDA];
    __shared__ __align__(16) __nv_bfloat16 Bh[BK * LDB], Bl[BK * LDB];
    __shared__ float sSc[128], sOf[128];

    int tid = threadIdx.x;
    int useAff = (gam != nullptr);
    if (useAff && tid < K) {
        const float* stat = g_stat + layer * 256;
        float mu  = stat[tid] / (float)NN;
        float ex2 = stat[K + tid] / (float)NN;
        float inv = rsqrtf(ex2 - mu * mu + BN_EPS);
        float sc  = gam[tid] * inv;
        sSc[tid] = sc;
        sOf[tid] = bet[tid] - mu * sc;
    }
    __syncthreads();

    const float* Wreg = W + (size_t)blockIdx.y * wRegStride;
    int m0 = blockIdx.x * BM;
    int nBase = blockIdx.y * BN;

    float4 aReg[NAR], bReg[NBR];

    auto loadA = [&](int k0) {
        #pragma unroll
        for (int f = 0; f < NAR; f++) {
            int fid = tid + f * 256;
            int r = fid >> 3, kq = fid & 7;
            int row = m0 + r;
            float4 vv = make_float4(0.f, 0.f, 0.f, 0.f);
            if (row < NN)
                vv = *reinterpret_cast<const float4*>(A + (size_t)row * K + k0 + kq * 4);
            if (useAff) {
                int kk = k0 + kq * 4;
                vv.x = fmaf(vv.x, sSc[kk + 0], sOf[kk + 0]);
                vv.y = fmaf(vv.y, sSc[kk + 1], sOf[kk + 1]);
                vv.z = fmaf(vv.z, sSc[kk + 2], sOf[kk + 2]);
                vv.w = fmaf(vv.w, sSc[kk + 3], sOf[kk + 3]);
            }
            aReg[f] = vv;
        }
    };
    auto loadB = [&](int k0) {
        #pragma unroll
        for (int f = 0; f < NBR; f++) {
            int fid = tid + f * 256;
            int kk = fid / (BN / 4);
            int nq = fid % (BN / 4);
            bReg[f] = *reinterpret_cast<const float4*>(
                Wreg + (size_t)(k0 + kk) * BN + nq * 4);
        }
    };
    auto storeAB = [&]() {
        #pragma unroll
        for (int f = 0; f < NAR; f++) {
            int fid = tid + f * 256;
            int r = fid >> 3, kq = fid & 7;
            float vs[4] = {aReg[f].x, aReg[f].y, aReg[f].z, aReg[f].w};
            #pragma unroll
            for (int j = 0; j < 4; j++) {
                __nv_bfloat16 h, l;
                split_bf16(vs[j], h, l);
                Ah[r * LDA + kq * 4 + j] = h;
                Al[r * LDA + kq * 4 + j] = l;
            }
        }
        #pragma unroll
        for (int f = 0; f < NBR; f++) {
            int fid = tid + f * 256;
            int kk = fid / (BN / 4);
            int nq = fid % (BN / 4);
            float vs[4] = {bReg[f].x, bReg[f].y, bReg[f].z, bReg[f].w};
            #pragma unroll
            for (int j = 0; j < 4; j++) {
                __nv_bfloat16 h, l;
                split_bf16(vs[j], h, l);
                Bh[kk * LDB + nq * 4 + j] = h;
                Bl[kk * LDB + nq * 4 + j] = l;
            }
        }
    };

    int lane = tid & 31, w = tid >> 5;
    int wm = (w & 3) * 32;        // warp m offset
    int wn = (w >> 2) * WN;       // warp n offset

    uint32_t ahB = (uint32_t)__cvta_generic_to_shared(Ah);
    uint32_t alB = (uint32_t)__cvta_generic_to_shared(Al);
    uint32_t bhB = (uint32_t)__cvta_generic_to_shared(Bh);
    uint32_t blB = (uint32_t)__cvta_generic_to_shared(Bl);

    float acc[2][NF][4];
    #pragma unroll
    for (int i = 0; i < 2; i++)
        #pragma unroll
        for (int j = 0; j < NF; j++)
            #pragma unroll
            for (int q = 0; q < 4; q++) acc[i][j][q] = 0.f;

    // prologue: stage tile 0
    loadA(0); loadB(0);
    storeAB();
    __syncthreads();

    for (int k0 = 0; k0 < K; k0 += BK) {
        bool hasNext = (k0 + BK) < K;
        if (hasNext) { loadA(k0 + BK); loadB(k0 + BK); }  // prefetch to regs

        #pragma unroll
        for (int ks = 0; ks < BK / 16; ks++) {
            int kk = ks * 16;
            uint32_t afh[2][4], afl[2][4];
            #pragma unroll
            for (int mf = 0; mf < 2; mf++) {
                uint32_t off = ((wm + mf * 16 + (lane & 15)) * LDA
                                + kk + (lane >> 4) * 8) * 2;
                ldsm4(afh[mf], ahB + off);
                ldsm4(afl[mf], alB + off);
            }
            #pragma unroll
            for (int ch = 0; ch < NF / 2; ch++) {
                uint32_t bfh[4], bfl[4];
                uint32_t off = ((kk + (lane & 15)) * LDB
                                + wn + ch * 16 + (lane >> 4) * 8) * 2;
                ldsm4t(bfh, bhB + off);
                ldsm4t(bfl, blB + off);
                #pragma unroll
                for (int mf = 0; mf < 2; mf++) {
                    #pragma unroll
                    for (int sub = 0; sub < 2; sub++) {
                        float* d = acc[mf][ch * 2 + sub];
                        mma16816(d, afh[mf], &bfh[sub * 2]);
                        mma16816(d, afh[mf], &bfl[sub * 2]);
                        mma16816(d, afl[mf], &bfh[sub * 2]);
                    }
                }
            }
        }
        __syncthreads();
        if (hasNext) {
            storeAB();
            __syncthreads();
        }
    }

    // ---- epilogue ----
    #pragma unroll
    for (int mf = 0; mf < 2; mf++) {
        int rbase = m0 + wm + mf * 16 + (lane >> 2);
        #pragma unroll
        for (int half = 0; half < 2; half++) {
            int row = rbase + half * 8;
            if (row >= NN) continue;
            float d = useDis ? g_dis[row] : 1.f;
            #pragma unroll
            for (int nf = 0; nf < NF; nf++) {
                int col = nBase + wn + nf * 8 + (lane & 3) * 2;
                float v0 = acc[mf][nf][half * 2 + 0] * d;
                float v1 = acc[mf][nf][half * 2 + 1] * d;
                if constexpr (OUTH) {
                    __half2 hv = __floats2half2_rn(v0, v1);
                    *reinterpret_cast<__half2*>((__half*)outp + (size_t)row * outStride + col) = hv;
                } else {
                    float2 fv = make_float2(v0, v1);
                    *reinterpret_cast<float2*>((float*)outp + (size_t)row * outStride + col) = fv;
                }
            }
        }
    }
}

// ---------------- CSR gather aggregation + bias + relu + BN stats ----------
// r[n,c] = relu(dis[n] * (hsh[n,c] + sum_{in-nbrs} hsh[src,c]) + bias[c])
template <int C>
__global__ void __launch_bounds__(256) k_agg(const float* __restrict__ bias, int layer)
{
    constexpr int V = C / 32;   // 2 or 4 channels per lane
    int warp = threadIdx.x >> 5, lane = threadIdx.x & 31;
    int n = blockIdx.x * 8 + warp;
    float* stat = g_stat + layer * 256;
    __shared__ float sh[2 * C];
    for (int t = threadIdx.x; t < 2 * C; t += 256) sh[t] = 0.f;
    __syncthreads();

    if (n < NN) {
        int s = g_start[n], e = g_start[n + 1];
        float bch[V];
        #pragma unroll
        for (int q = 0; q < V; q++) bch[q] = bias[lane * V + q];
        float acc[V];

        auto loadrow = [&](int row, float* f) {
            if constexpr (C == 128) {
                float2 raw = *reinterpret_cast<const float2*>(
                    g_hsh + (size_t)row * C + lane * 4);
                __half2 h01 = *reinterpret_cast<__half2*>(&raw.x);
                __half2 h23 = *reinterpret_cast<__half2*>(&raw.y);
                float2 f01 = __half22float2(h01);
                float2 f23 = __half22float2(h23);
                f[0] = f01.x; f[1] = f01.y; f[2] = f23.x; f[3] = f23.y;
            } else {
                __half2 h = *reinterpret_cast<const __half2*>(
                    g_hsh + (size_t)row * C + lane * 2);
                float2 ff = __half22float2(h);
                f[0] = ff.x; f[1] = ff.y;
            }
        };

        loadrow(n, acc);
        int k = s;
        for (; k + 4 <= e; k += 4) {
            int s0 = g_csr[k], s1 = g_csr[k + 1], s2 = g_csr[k + 2], s3 = g_csr[k + 3];
            float f0[V], f1[V], f2[V], f3[V];
            loadrow(s0, f0); loadrow(s1, f1); loadrow(s2, f2); loadrow(s3, f3);
            #pragma unroll
            for (int q = 0; q < V; q++)
                acc[q] += (f0[q] + f1[q]) + (f2[q] + f3[q]);
        }
        for (; k < e; k++) {
            float f0[V];
            loadrow(g_csr[k], f0);
            #pragma unroll
            for (int q = 0; q < V; q++) acc[q] += f0[q];
        }
        float dn = g_dis[n];
        #pragma unroll
        for (int q = 0; q < V; q++) {
            int c = lane * V + q;
            float t = fmaxf(acc[q] * dn + bch[q], 0.f);
            g_r[(size_t)n * C + c] = t;
            atomicAdd(&sh[c], t);
            atomicAdd(&sh[C + c], t * t);
        }
    }
    __syncthreads();
    for (int t = threadIdx.x; t < 2 * C; t += 256)
        atomicAdd(&stat[t], sh[t]);
}

// ---------------- edge-pair scoring ---------------------------------------
__global__ void __launch_bounds__(256)
k_score(const int* __restrict__ src, const int* __restrict__ dst,
        const float* __restrict__ fcb1, const float* __restrict__ fcW2,
        const float* __restrict__ fcb2, float* __restrict__ out)
{
    int warp = threadIdx.x >> 5, lane = threadIdx.x & 31;
    int p = blockIdx.x * 8 + warp;
    if (p >= NP) return;
    int s = src[p], d = dst[p];
    float4 uu = *reinterpret_cast<const float4*>(g_uv + (size_t)s * 256 + lane * 4);
    float4 vv = *reinterpret_cast<const float4*>(g_uv + (size_t)d * 256 + 128 + lane * 4);
    float4 bb = *reinterpret_cast<const float4*>(fcb1 + lane * 4);
    float4 ww = *reinterpret_cast<const float4*>(fcW2 + lane * 4);
    float h0 = fmaxf(uu.x + vv.x + bb.x, 0.f);
    float h1 = fmaxf(uu.y + vv.y + bb.y, 0.f);
    float h2 = fmaxf(uu.z + vv.z + bb.z, 0.f);
    float h3 = fmaxf(uu.w + vv.w + bb.w, 0.f);
    float part = h0 * ww.x + h1 * ww.y + h2 * ww.z + h3 * ww.w;
    #pragma unroll
    for (int off = 16; off; off >>= 1)
        part += __shfl_down_sync(0xffffffffu, part, off);
    if (lane == 0) out[p] = part + fcb2[0];
}

// ---------------- host launch ---------------------------------------------
extern "C" void kernel_launch(void* const* d_in, const int* in_sizes, int n_in,
                              void* d_out, int out_size)
{
    const float* x    = (const float*)d_in[0];
    const int*   ei   = (const int*)  d_in[1];
    const int*   src  = (const int*)  d_in[2];
    const int*   dst  = (const int*)  d_in[3];
    const float* W1   = (const float*)d_in[4];
    const float* b1   = (const float*)d_in[5];
    const float* W2   = (const float*)d_in[6];
    const float* b2   = (const float*)d_in[7];
    const float* W3   = (const float*)d_in[8];
    const float* b3   = (const float*)d_in[9];
    const float* g1   = (const float*)d_in[10];
    const float* bt1  = (const float*)d_in[11];
    const float* g2   = (const float*)d_in[12];
    const float* bt2  = (const float*)d_in[13];
    const float* g3   = (const float*)d_in[14];
    const float* bt3  = (const float*)d_in[15];
    const float* fcW1 = (const float*)d_in[16];
    const float* fcb1 = (const float*)d_in[17];
    const float* fcW2 = (const float*)d_in[18];
    const float* fcb2 = (const float*)d_in[19];
    float* out = (float*)d_out;

    void *hsh; float *r, *uv;
    cudaGetSymbolAddress((void**)&hsh, g_hsh);
    cudaGetSymbolAddress((void**)&r,   g_r);
    cudaGetSymbolAddress((void**)&uv,  g_uv);

    const int NB = (NN + 255) / 256;     // 196
    const int EB = NE / 256;             // 6250
    const int GB = (NN + 127) / 128;     // 391
    const int AB = (NN + 7) / 8;         // 6250

    // graph preprocessing: degrees(+rank), dis, CSR
    k_zero_cnt<<<NB, 256>>>();
    k_count<<<EB, 256>>>(ei);
    k_scan<<<1, 1024>>>();
    k_fill<<<EB, 256>>>(ei);

    // layer 1: x[N,128] @ W1[128,64] -> hsh (dis-scaled, fp16); agg
    k_gemm<64, 32, 1><<<GB, 256>>>(x, W1, hsh, 128, nullptr, nullptr, 0, 1, 0, 64);
    k_agg<64><<<AB, 256>>>(b1, 0);

    // layer 2: bn1(z1)[N,64] @ W2[64,128]
    k_gemm<128, 64, 1><<<GB, 256>>>(r, W2, hsh, 64, g1, bt1, 0, 1, 0, 128);
    k_agg<128><<<AB, 256>>>(b2, 1);

    // layer 3: bn2(z2)[N,128] @ W3[128,128]
    k_gemm<128, 64, 1><<<GB, 256>>>(r, W3, hsh, 128, g2, bt2, 1, 1, 0, 128);
    k_agg<128><<<AB, 256>>>(b3, 2);

    // fused per-node MLP halves: uv[:,0:128]=bn3(z3)@fcW1[:128,:], uv[:,128:256]=bn3(z3)@fcW1[128:,:]
    k_gemm<128, 64, 0><<<dim3(GB, 2), 256>>>(r, fcW1, uv, 128, g3, bt3, 2, 0,
                                             128 * 128, 256);

    // score pairs
    k_score<<<(NP + 7) / 8, 256>>>(src, dst, fcb1, fcW2, fcb2, out);
}